// round 3
// baseline (speedup 1.0000x reference)
#include <cuda_runtime.h>
#include <math.h>

namespace {

constexpr int T_     = 29;        // time samples per segment
constexpr int NSEG   = 3;
constexpr int B_     = 16384;
constexpr int TB     = 256;       // batch elements per block (8 warps)
constexpr int NW     = TB / 32;
constexpr int TSPLIT = 4;         // t-range quarters
constexpr float DS_  = 0.005f;

// Constant-curvature transfer (M, v) for arclength s: R(s)=R0*M, r(s)=r0+R0*v
__device__ __forceinline__ void curv_Mv(float ux, float uy, float s,
                                        float M[9], float v[3])
{
    float w2 = fmaf(ux, ux, uy * uy);
    float w  = sqrtf(w2);
    float th = s * w;
    float b, c;
    if (th < 1e-4f) {
        b = s;                    // sinθ/ω ≈ s
        c = 0.5f * s * s;         // (1-cosθ)/ω² ≈ s²/2
    } else {
        float sh, ch;
        sincosf(0.5f * th, &sh, &ch);
        b = (2.0f * sh * ch) / w;     // sinθ/ω
        c = (2.0f * sh * sh) / w2;    // (1-cosθ)/ω², cancellation-free
    }
    float ct = fmaf(-c, w2, 1.0f);    // cosθ
    float bx = b * ux, by = b * uy;
    float cx = c * ux, cy = c * uy;
    M[0] = fmaf(-cy, uy, 1.0f);  M[1] = cx * uy;              M[2] = by;
    M[3] = M[1];                 M[4] = fmaf(-cx, ux, 1.0f);  M[5] = -bx;
    M[6] = -by;                  M[7] = bx;                   M[8] = ct;
    v[0] = cy;  v[1] = -cx;  v[2] = b;
}

__device__ __forceinline__ void apply_Mv(float r[3], float R[9],
                                         const float M[9], const float v[3])
{
#pragma unroll
    for (int i = 0; i < 3; i++) {
        float a0 = R[3 * i], a1 = R[3 * i + 1], a2 = R[3 * i + 2];
        r[i] += a0 * v[0] + a1 * v[1] + a2 * v[2];
        R[3 * i]     = a0 * M[0] + a1 * M[3] + a2 * M[6];
        R[3 * i + 1] = a0 * M[1] + a1 * M[4] + a2 * M[7];
        R[3 * i + 2] = a0 * M[2] + a1 * M[5] + a2 * M[8];
    }
}

__device__ __forceinline__ void advance_state(float r[3], float R[9],
                                              float ux, float uy, float s)
{
    float M[9], v[3];
    curv_Mv(ux, uy, s, M, v);
    apply_Mv(r, R, M, v);
}

__global__ void __launch_bounds__(TB) pcc_kernel(const float* __restrict__ actions,
                                                 float* __restrict__ out)
{
    // per-warp 32x14 tiles (NW*448 floats = 3584 >= 2304 action-stage floats)
    __shared__ float sm[NW][32 * 14];
    const int tid  = threadIdx.x;
    const int lane = tid & 31;
    const int w    = tid >> 5;
    const int bx   = blockIdx.x;
    const int seg  = blockIdx.y / TSPLIT;
    const int tq   = blockIdx.y - seg * TSPLIT;
    const int t0   = (tq * T_) / TSPLIT;
    const int t1   = ((tq + 1) * T_) / TSPLIT;
    const int b0   = bx * TB;

    // Stage this chunk's actions coalesced through smem (stride-9 reads
    // conflict-free: gcd(9,32)=1). Block-wide barriers only here.
    float* stage = &sm[0][0];
#pragma unroll
    for (int i = 0; i < 9; i++)
        stage[tid + i * TB] = actions[(size_t)b0 * 9 + tid + i * TB];
    __syncthreads();
    float a[9];
#pragma unroll
    for (int i = 0; i < 9; i++) a[i] = stage[tid * 9 + i];
    __syncthreads();

    // Chain through prior segments (clamped endpoints), pick up own params.
    float r[3] = {0.f, 0.f, 0.f};
    float R[9] = {1.f, 0.f, 0.f, 0.f, 1.f, 0.f, 0.f, 0.f, 1.f};
    float ux = 0.f, uy = 0.f;
    int len = 0;
#pragma unroll
    for (int n = 0; n < NSEG; n++) {
        if (n > seg) break;
        float l  = 0.1f + a[3 * n];
        float ld = l * 0.0075f;
        ux  = a[3 * n + 2] / (-ld);
        uy  = a[3 * n + 1] / ld;
        len = (int)(l / DS_);                  // replicates (l/DS).astype(int32)
        if (n < seg) advance_state(r, R, ux, uy, (float)len * DS_);
    }

    // Jump to this t-range's start (clamped), then march with constant step.
    int tt0 = t0 < len ? t0 : len;
    advance_state(r, R, ux, uy, (float)tt0 * DS_);
    float Ms[9], vs[3];
    curv_Mv(ux, uy, DS_, Ms, vs);

    float* tile = &sm[w][0];
    for (int t = t0; t < t1; ++t) {
        // pack state as 7 float2: (r0,r1)(r2,R0)(R1,R2)(R3,R4)(R5,R6)(R7,R8)(ux,uy)
        float2* pk = reinterpret_cast<float2*>(tile + lane * 14);
        pk[0] = make_float2(r[0], r[1]);
        pk[1] = make_float2(r[2], R[0]);
        pk[2] = make_float2(R[1], R[2]);
        pk[3] = make_float2(R[3], R[4]);
        pk[4] = make_float2(R[5], R[6]);
        pk[5] = make_float2(R[7], R[8]);
        pk[6] = make_float2(ux,   uy);
        __syncwarp();

        const float2* src = reinterpret_cast<const float2*>(tile);
        float2* dst = reinterpret_cast<float2*>(
            out + (size_t)(seg * T_ + t) * ((size_t)B_ * 14)
                + (size_t)(b0 + w * 32) * 14);
#pragma unroll
        for (int i = 0; i < 7; i++)
            dst[lane + i * 32] = src[lane + i * 32];

        if (t < len) apply_Mv(r, R, Ms, vs);   // independent of the LDS/STG above
        __syncwarp();
    }
}

} // namespace

extern "C" void kernel_launch(void* const* d_in, const int* in_sizes, int n_in,
                              void* d_out, int out_size)
{
    (void)in_sizes; (void)n_in; (void)out_size;
    const float* actions = (const float*)d_in[0];
    float* out = (float*)d_out;
    dim3 grid(B_ / TB, NSEG * TSPLIT);
    pcc_kernel<<<grid, TB>>>(actions, out);
}

// round 4
// speedup vs baseline: 1.5053x; 1.5053x over previous
#include <cuda_runtime.h>
#include <math.h>

namespace {

constexpr int T_     = 29;        // time samples per segment
constexpr int NSEG   = 3;
constexpr int B_     = 16384;
constexpr int TB     = 256;       // batch elements per block (8 warps)
constexpr int NW     = TB / 32;
constexpr int TSPLIT = 4;         // t-range quarters
constexpr float DS_  = 0.005f;

// Constant-curvature transfer (M, v) for arclength s: R(s)=R0*M, r(s)=r0+R0*v
// Fast-math version: MUFU sincos + fast reciprocal (abs err ~1e-6, fine vs 1e-3 tol).
__device__ __forceinline__ void curv_Mv(float ux, float uy, float s,
                                        float M[9], float v[3])
{
    float w2 = fmaf(ux, ux, uy * uy);
    float w  = sqrtf(w2);
    float th = s * w;
    float b, c;
    if (th < 1e-4f) {
        b = s;                    // sinθ/ω ≈ s
        c = 0.5f * s * s;         // (1-cosθ)/ω² ≈ s²/2
    } else {
        float sh, ch;
        __sincosf(0.5f * th, &sh, &ch);           // MUFU.SIN/COS
        float rw = __fdividef(1.0f, w);
        b = (2.0f * sh * ch) * rw;                // sinθ/ω
        c = (2.0f * sh * sh) * rw * rw;           // (1-cosθ)/ω², cancellation-free
    }
    float ct = fmaf(-c, w2, 1.0f);    // cosθ
    float bx = b * ux, by = b * uy;
    float cx = c * ux, cy = c * uy;
    M[0] = fmaf(-cy, uy, 1.0f);  M[1] = cx * uy;              M[2] = by;
    M[3] = M[1];                 M[4] = fmaf(-cx, ux, 1.0f);  M[5] = -bx;
    M[6] = -by;                  M[7] = bx;                   M[8] = ct;
    v[0] = cy;  v[1] = -cx;  v[2] = b;
}

__device__ __forceinline__ void apply_Mv(float r[3], float R[9],
                                         const float M[9], const float v[3])
{
#pragma unroll
    for (int i = 0; i < 3; i++) {
        float a0 = R[3 * i], a1 = R[3 * i + 1], a2 = R[3 * i + 2];
        r[i] += a0 * v[0] + a1 * v[1] + a2 * v[2];
        R[3 * i]     = a0 * M[0] + a1 * M[3] + a2 * M[6];
        R[3 * i + 1] = a0 * M[1] + a1 * M[4] + a2 * M[7];
        R[3 * i + 2] = a0 * M[2] + a1 * M[5] + a2 * M[8];
    }
}

__device__ __forceinline__ void advance_state(float r[3], float R[9],
                                              float ux, float uy, float s)
{
    float M[9], v[3];
    curv_Mv(ux, uy, s, M, v);
    apply_Mv(r, R, M, v);
}

__global__ void __launch_bounds__(TB) pcc_kernel(const float* __restrict__ actions,
                                                 float* __restrict__ out)
{
    // per-warp double-buffered 32x14 tiles; buffer 0 also stages actions
    __shared__ float sm[NW][2][32 * 14];
    const int tid  = threadIdx.x;
    const int lane = tid & 31;
    const int w    = tid >> 5;
    const int bx   = blockIdx.x;
    const int seg  = blockIdx.y / TSPLIT;
    const int tq   = blockIdx.y - seg * TSPLIT;
    const int t0   = (tq * T_) / TSPLIT;
    const int t1   = ((tq + 1) * T_) / TSPLIT;
    const int b0   = bx * TB;

    // Stage this chunk's actions coalesced through smem (stride-9 reads
    // conflict-free: gcd(9,32)=1). Block-wide barriers only here.
    float* stage = &sm[0][0][0];
#pragma unroll
    for (int i = 0; i < 9; i++)
        stage[tid + i * TB] = actions[(size_t)b0 * 9 + tid + i * TB];
    __syncthreads();
    float a[9];
#pragma unroll
    for (int i = 0; i < 9; i++) a[i] = stage[tid * 9 + i];
    __syncthreads();

    // Chain through prior segments (clamped endpoints), pick up own params.
    float r[3] = {0.f, 0.f, 0.f};
    float R[9] = {1.f, 0.f, 0.f, 0.f, 1.f, 0.f, 0.f, 0.f, 1.f};
    float ux = 0.f, uy = 0.f;
    int len = 0;
#pragma unroll
    for (int n = 0; n < NSEG; n++) {
        if (n > seg) break;
        float l  = 0.1f + a[3 * n];
        float ld = l * 0.0075f;
        ux  = __fdividef(a[3 * n + 2], -ld);
        uy  = __fdividef(a[3 * n + 1],  ld);
        len = (int)(l / DS_);           // IEEE-exact: replicates (l/DS).astype(int32)
        if (n < seg) advance_state(r, R, ux, uy, (float)len * DS_);
    }

    // Jump to this t-range's start (clamped), then march with constant step.
    int tt0 = t0 < len ? t0 : len;
    advance_state(r, R, ux, uy, (float)tt0 * DS_);
    float Ms[9], vs[3];
    curv_Mv(ux, uy, DS_, Ms, vs);

    for (int t = t0; t < t1; ++t) {
        float* tile = &sm[w][(t - t0) & 1][0];
        // pack state as 7 float2: (r0,r1)(r2,R0)(R1,R2)(R3,R4)(R5,R6)(R7,R8)(ux,uy)
        float2* pk = reinterpret_cast<float2*>(tile + lane * 14);
        pk[0] = make_float2(r[0], r[1]);
        pk[1] = make_float2(r[2], R[0]);
        pk[2] = make_float2(R[1], R[2]);
        pk[3] = make_float2(R[3], R[4]);
        pk[4] = make_float2(R[5], R[6]);
        pk[5] = make_float2(R[7], R[8]);
        pk[6] = make_float2(ux,   uy);
        __syncwarp();

        const float2* src = reinterpret_cast<const float2*>(tile);
        float2* dst = reinterpret_cast<float2*>(
            out + (size_t)(seg * T_ + t) * ((size_t)B_ * 14)
                + (size_t)(b0 + w * 32) * 14);
#pragma unroll
        for (int i = 0; i < 7; i++)
            dst[lane + i * 32] = src[lane + i * 32];

        if (t < len) apply_Mv(r, R, Ms, vs);   // overlaps with LDS/STG above
    }
}

} // namespace

extern "C" void kernel_launch(void* const* d_in, const int* in_sizes, int n_in,
                              void* d_out, int out_size)
{
    (void)in_sizes; (void)n_in; (void)out_size;
    const float* actions = (const float*)d_in[0];
    float* out = (float*)d_out;
    dim3 grid(B_ / TB, NSEG * TSPLIT);
    pcc_kernel<<<grid, TB>>>(actions, out);
}